// round 14
// baseline (speedup 1.0000x reference)
#include <cuda_runtime.h>
#include <math.h>
#include <stdint.h>

// ---------------------------------------------------------------------------
// B=8, C=512, H=W=128, WS=8, NH=8, hd=64, L=64, N=256 windows/batch
// TOKS = 8*256*64 = 131072
// ---------------------------------------------------------------------------
#define TOKS 131072

__device__ float    g_t  [(size_t)TOKS * 512];   // residual (fp32)
__device__ uint32_t g_xn [(size_t)TOKS * 256];   // LN out (bf16x2)
__device__ uint32_t g_qkv[(size_t)TOKS * 768];   // qkv (bf16x2)
__device__ uint32_t g_o  [(size_t)TOKS * 256];   // attn out (bf16x2)
__device__ uint32_t g_h  [(size_t)TOKS * 1024];  // mlp hidden (bf16x2)

// weights packed as PAIRED k-words (uint2):
//   Bp[j][n][c] = ( word(8j+c, n), word(8j+c+4, n) )
#define WQKV2_OFF 0
#define WOUT2_OFF 196608
#define W1_2_OFF  262144
#define W2_2_OFF  524288
#define WTOT2     786432
__device__ uint2 g_w[WTOT2];

__device__ __forceinline__ uint32_t packbf(float lo, float hi) {
    uint32_t u;
    asm("cvt.rn.bf16x2.f32 %0, %1, %2;" : "=r"(u) : "f"(hi), "f"(lo));
    return u;
}

// ---------------------------------------------------------------------------
// Weight pack: fp32 [K][N] -> paired-word uint2 layout
// ---------------------------------------------------------------------------
__global__ void __launch_bounds__(256) wpack_k(
    const float* __restrict__ wqkv, const float* __restrict__ wout,
    const float* __restrict__ w1, const float* __restrict__ w2,
    uint2* __restrict__ dst)
{
    int idx = blockIdx.x * 256 + threadIdx.x;
    const float* src;
    int N, u;
    if (idx < WOUT2_OFF)      { src = wqkv; N = 1536; u = idx; }
    else if (idx < W1_2_OFF)  { src = wout; N = 512;  u = idx - WOUT2_OFF; }
    else if (idx < W2_2_OFF)  { src = w1;   N = 2048; u = idx - W1_2_OFF; }
    else                      { src = w2;   N = 512;  u = idx - W2_2_OFF; }
    int c  = u & 3;
    int nc = u >> 2;
    int n  = nc % N;
    int j  = nc / N;
    int kp0 = 8 * j + c;
    int kp1 = kp0 + 4;
    uint2 out;
    out.x = packbf(src[(2 * kp0) * N + n], src[(2 * kp0 + 1) * N + n]);
    out.y = packbf(src[(2 * kp1) * N + n], src[(2 * kp1 + 1) * N + n]);
    dst[idx] = out;
}

// ---------------------------------------------------------------------------
// Window partition + LayerNorm1, coalesced (one CTA per 8-token window row).
// ---------------------------------------------------------------------------
__global__ void __launch_bounds__(256) ln1_part_k(
    const float* __restrict__ x, const float* __restrict__ gamma,
    const float* __restrict__ beta, float* __restrict__ t, uint32_t* __restrict__ xn)
{
    int tid  = threadIdx.x;
    int tok0 = blockIdx.x << 3;
    int b  = tok0 >> 14;
    int n  = (tok0 >> 6) & 255;
    int l0 = tok0 & 63;
    int h  = ((n >> 4) << 3) | (l0 >> 3);
    int w0 = (n & 15) << 3;
    int c0 = tid << 1;

    size_t base0 = ((size_t)(b * 512 + c0)) * 16384 + (size_t)(h << 7) + w0;

    float va[8], vb[8];
    {
        float4 p0 = *(const float4*)(x + base0);
        float4 p1 = *(const float4*)(x + base0 + 4);
        float4 p2 = *(const float4*)(x + base0 + 16384);
        float4 p3 = *(const float4*)(x + base0 + 16388);
        va[0]=p0.x; va[1]=p0.y; va[2]=p0.z; va[3]=p0.w;
        va[4]=p1.x; va[5]=p1.y; va[6]=p1.z; va[7]=p1.w;
        vb[0]=p2.x; vb[1]=p2.y; vb[2]=p2.z; vb[3]=p2.w;
        vb[4]=p3.x; vb[5]=p3.y; vb[6]=p3.z; vb[7]=p3.w;
    }

    float s[8], s2[8];
#pragma unroll
    for (int ww = 0; ww < 8; ww++) {
        s[ww]  = va[ww] + vb[ww];
        s2[ww] = va[ww] * va[ww] + vb[ww] * vb[ww];
    }
#pragma unroll
    for (int off = 16; off; off >>= 1) {
#pragma unroll
        for (int ww = 0; ww < 8; ww++) {
            s[ww]  += __shfl_xor_sync(0xffffffffu, s[ww],  off);
            s2[ww] += __shfl_xor_sync(0xffffffffu, s2[ww], off);
        }
    }

    __shared__ float red[8][16];
    __shared__ float mr[16];
    int warp = tid >> 5, lane = tid & 31;
    if (lane == 0) {
#pragma unroll
        for (int ww = 0; ww < 8; ww++) {
            red[warp][ww]     = s[ww];
            red[warp][8 + ww] = s2[ww];
        }
    }
    __syncthreads();
    if (tid < 8) {
        float ts = 0.f, ts2 = 0.f;
#pragma unroll
        for (int wp = 0; wp < 8; wp++) {
            ts  += red[wp][tid];
            ts2 += red[wp][8 + tid];
        }
        float mu  = ts * (1.f / 512.f);
        float var = ts2 * (1.f / 512.f) - mu * mu;
        mr[tid]     = mu;
        mr[8 + tid] = rsqrtf(var + 1e-5f);
    }
    __syncthreads();

    float ga = gamma[c0], gb = gamma[c0 + 1];
    float ba = beta[c0],  bb = beta[c0 + 1];
#pragma unroll
    for (int ww = 0; ww < 8; ww++) {
        int tok = tok0 + ww;
        float mu = mr[ww], rs = mr[8 + ww];
        float n0 = (va[ww] - mu) * rs * ga + ba;
        float n1 = (vb[ww] - mu) * rs * gb + bb;
        *(float2*)&t[(size_t)tok * 512 + c0] = make_float2(va[ww], vb[ww]);
        xn[(size_t)tok * 256 + tid] = packbf(n0, n1);
    }
}

// ---------------------------------------------------------------------------
// LayerNorm2: fp32 src (t) -> bf16 xn
// ---------------------------------------------------------------------------
__global__ void __launch_bounds__(128) ln2_k(
    const float* __restrict__ src, const float* __restrict__ gamma,
    const float* __restrict__ beta, uint32_t* __restrict__ xn)
{
    int tok = blockIdx.x;
    int tid = threadIdx.x;
    int c0 = tid << 2;
    float4 v4 = *(const float4*)&src[(size_t)tok * 512 + c0];
    float v[4] = {v4.x, v4.y, v4.z, v4.w};
    float s = v[0] + v[1] + v[2] + v[3];
    float s2 = v[0]*v[0] + v[1]*v[1] + v[2]*v[2] + v[3]*v[3];
#pragma unroll
    for (int off = 16; off; off >>= 1) {
        s  += __shfl_xor_sync(0xffffffffu, s,  off);
        s2 += __shfl_xor_sync(0xffffffffu, s2, off);
    }
    __shared__ float sh[8];
    int wid = tid >> 5, lane = tid & 31;
    if (lane == 0) { sh[wid] = s; sh[4 + wid] = s2; }
    __syncthreads();
    s  = sh[0] + sh[1] + sh[2] + sh[3];
    s2 = sh[4] + sh[5] + sh[6] + sh[7];
    float mu  = s  * (1.f / 512.f);
    float var = s2 * (1.f / 512.f) - mu * mu;
    float rs  = rsqrtf(var + 1e-5f);

    float nv[4];
#pragma unroll
    for (int k = 0; k < 4; k++)
        nv[k] = (v[k] - mu) * rs * gamma[c0 + k] + beta[c0 + k];
    uint2 pw = make_uint2(packbf(nv[0], nv[1]), packbf(nv[2], nv[3]));
    *(uint2*)&xn[(size_t)tok * 256 + (tid << 1)] = pw;
}

// ---------------------------------------------------------------------------
// ldmatrix / mma helpers
// ---------------------------------------------------------------------------
__device__ __forceinline__ void ldsm4(uint32_t& r0, uint32_t& r1, uint32_t& r2,
                                      uint32_t& r3, uint32_t addr) {
    asm volatile("ldmatrix.sync.aligned.m8n8.x4.shared.b16 {%0,%1,%2,%3}, [%4];"
                 : "=r"(r0), "=r"(r1), "=r"(r2), "=r"(r3) : "r"(addr));
}
__device__ __forceinline__ void ldsm2(uint32_t& r0, uint32_t& r1, uint32_t addr) {
    asm volatile("ldmatrix.sync.aligned.m8n8.x2.shared.b16 {%0,%1}, [%2];"
                 : "=r"(r0), "=r"(r1) : "r"(addr));
}
__device__ __forceinline__ void ldsm2t(uint32_t& r0, uint32_t& r1, uint32_t addr) {
    asm volatile("ldmatrix.sync.aligned.m8n8.x2.trans.shared.b16 {%0,%1}, [%2];"
                 : "=r"(r0), "=r"(r1) : "r"(addr));
}
__device__ __forceinline__ void lds64(uint32_t& r0, uint32_t& r1, uint32_t addr) {
    asm volatile("ld.shared.v2.u32 {%0,%1}, [%2];"
                 : "=r"(r0), "=r"(r1) : "r"(addr));
}
__device__ __forceinline__ void mma_bf16_a(float* d, uint32_t a0, uint32_t a1,
                                           uint32_t a2, uint32_t a3,
                                           uint32_t b0, uint32_t b1) {
    asm volatile(
        "mma.sync.aligned.m16n8k16.row.col.f32.bf16.bf16.f32 "
        "{%0,%1,%2,%3}, {%4,%5,%6,%7}, {%8,%9}, {%0,%1,%2,%3};"
        : "+f"(d[0]), "+f"(d[1]), "+f"(d[2]), "+f"(d[3])
        : "r"(a0), "r"(a1), "r"(a2), "r"(a3), "r"(b0), "r"(b1));
}

// ---------------------------------------------------------------------------
// Tensor-core attention (unchanged, 132us)
// ---------------------------------------------------------------------------
#define ATS 36

__global__ void __launch_bounds__(128) attn_k(
    const uint32_t* __restrict__ qkv, uint32_t* __restrict__ o)
{
    __shared__ uint32_t sm[3 * 64 * ATS];
    uint32_t* qs = sm;
    uint32_t* ks = sm + 64 * ATS;
    uint32_t* vs = sm + 2 * 64 * ATS;

    int tid  = threadIdx.x;
    int lane = tid & 31;
    int warp = tid >> 5;
    int win  = blockIdx.x >> 3;
    int head = blockIdx.x & 7;

    {
        int row = tid >> 1, half = tid & 1;
        size_t gbase = (size_t)(win * 64 + row) * 768 + head * 32 + half * 16;
        int sbase = row * ATS + half * 16;
#pragma unroll
        for (int sec = 0; sec < 3; sec++) {
            const uint4* src = (const uint4*)(qkv + gbase + sec * 256);
            uint4* dst = (uint4*)(sm + sec * 64 * ATS + sbase);
            dst[0] = src[0]; dst[1] = src[1]; dst[2] = src[2]; dst[3] = src[3];
        }
    }
    __syncthreads();

    uint32_t qs_u = (uint32_t)__cvta_generic_to_shared(qs);
    uint32_t ks_u = (uint32_t)__cvta_generic_to_shared(ks);
    uint32_t vs_u = (uint32_t)__cvta_generic_to_shared(vs);

    int r0  = warp << 4;
    int l8  = lane & 7;
    int l16 = lane & 15;

    uint32_t qaddr = qs_u + (uint32_t)((r0 + l8 + (lane & 8)) * ATS + ((lane & 16) >> 2)) * 4u;
    uint32_t kaddr = ks_u + (uint32_t)((l16 & 7) * ATS + ((l16 & 8) >> 1)) * 4u;
    uint32_t vaddr = vs_u + (uint32_t)(((l16 & 7) + (l16 & 8)) * ATS) * 4u;

    float sacc[8][4];
#pragma unroll
    for (int nt = 0; nt < 8; nt++)
#pragma unroll
        for (int e = 0; e < 4; e++) sacc[nt][e] = 0.f;

#pragma unroll
    for (int kt = 0; kt < 4; kt++) {
        uint32_t a0, a1, a2, a3;
        ldsm4(a0, a1, a2, a3, qaddr + (uint32_t)(kt * 8) * 4u);
#pragma unroll
        for (int nt = 0; nt < 8; nt++) {
            uint32_t b0, b1;
            ldsm2(b0, b1, kaddr + (uint32_t)(nt * 8 * ATS + kt * 8) * 4u);
            mma_bf16_a(sacc[nt], a0, a1, a2, a3, b0, b1);
        }
    }

    const float scl = 1.f / 4096.f;
#pragma unroll
    for (int nt = 0; nt < 8; nt++)
#pragma unroll
        for (int e = 0; e < 4; e++) sacc[nt][e] *= scl;

    float m0 = -1e30f, m1 = -1e30f;
#pragma unroll
    for (int nt = 0; nt < 8; nt++) {
        m0 = fmaxf(m0, fmaxf(sacc[nt][0], sacc[nt][1]));
        m1 = fmaxf(m1, fmaxf(sacc[nt][2], sacc[nt][3]));
    }
    m0 = fmaxf(m0, __shfl_xor_sync(0xffffffffu, m0, 1));
    m0 = fmaxf(m0, __shfl_xor_sync(0xffffffffu, m0, 2));
    m1 = fmaxf(m1, __shfl_xor_sync(0xffffffffu, m1, 1));
    m1 = fmaxf(m1, __shfl_xor_sync(0xffffffffu, m1, 2));

    float sum0 = 0.f, sum1 = 0.f;
#pragma unroll
    for (int nt = 0; nt < 8; nt++) {
        sacc[nt][0] = __expf(sacc[nt][0] - m0); sum0 += sacc[nt][0];
        sacc[nt][1] = __expf(sacc[nt][1] - m0); sum0 += sacc[nt][1];
        sacc[nt][2] = __expf(sacc[nt][2] - m1); sum1 += sacc[nt][2];
        sacc[nt][3] = __expf(sacc[nt][3] - m1); sum1 += sacc[nt][3];
    }
    sum0 += __shfl_xor_sync(0xffffffffu, sum0, 1);
    sum0 += __shfl_xor_sync(0xffffffffu, sum0, 2);
    sum1 += __shfl_xor_sync(0xffffffffu, sum1, 1);
    sum1 += __shfl_xor_sync(0xffffffffu, sum1, 2);
    float inv0 = 1.f / sum0, inv1 = 1.f / sum1;

    uint32_t pw[4][4];
#pragma unroll
    for (int kt = 0; kt < 4; kt++) {
        pw[kt][0] = packbf(sacc[2*kt    ][0] * inv0, sacc[2*kt    ][1] * inv0);
        pw[kt][1] = packbf(sacc[2*kt    ][2] * inv1, sacc[2*kt    ][3] * inv1);
        pw[kt][2] = packbf(sacc[2*kt + 1][0] * inv0, sacc[2*kt + 1][1] * inv0);
        pw[kt][3] = packbf(sacc[2*kt + 1][2] * inv1, sacc[2*kt + 1][3] * inv1);
    }

    float oacc[8][4];
#pragma unroll
    for (int nt = 0; nt < 8; nt++)
#pragma unroll
        for (int e = 0; e < 4; e++) oacc[nt][e] = 0.f;

#pragma unroll
    for (int kt = 0; kt < 4; kt++) {
#pragma unroll
        for (int nt = 0; nt < 8; nt++) {
            uint32_t b0, b1;
            ldsm2t(b0, b1, vaddr + (uint32_t)(kt * 16 * ATS + nt * 4) * 4u);
            mma_bf16_a(oacc[nt], pw[kt][0], pw[kt][1], pw[kt][2], pw[kt][3], b0, b1);
        }
    }

    int r  = lane >> 2;
    int cq = lane & 3;
    uint32_t* ob = o + (size_t)(win * 64 + r0 + r) * 256 + head * 32 + cq;
#pragma unroll
    for (int nt = 0; nt < 8; nt++) {
        ob[nt * 4]            = packbf(oacc[nt][0], oacc[nt][1]);
        ob[8 * 256 + nt * 4]  = packbf(oacc[nt][2], oacc[nt][3]);
    }
}

// ---------------------------------------------------------------------------
// BF16 tensor-core GEMM: CTA 128x128, 128 threads = 4 warps (2Mx2N),
// warp tile 64x64. BK=64, 3-stage cp.async, ldsm4 A-frags,
// LDS.64 paired B-frags with register double buffering.
//   MODE 0: Cw = bf16(A@B + bias)
//   MODE 1: Cf += A@B + bias
//   MODE 2: Cw = bf16(gelu(A@B + bias))
//   MODE 3: out[x-layout] = Cf + A@B + bias
// ---------------------------------------------------------------------------
#define AS_STRIDE 36
#define AS_ELEMS (128 * AS_STRIDE)          // 4608 words
#define BS_ELEMS 4096                       // words (2048 uint2)
#define STAGE_ELEMS (AS_ELEMS + BS_ELEMS)   // 8704 words
#define BG_SMEM (3 * STAGE_ELEMS * 4)       // 104448 B

__device__ __forceinline__ float gelu_exact(float v) {
    return 0.5f * v * (1.0f + erff(v * 0.70710678118654752440f));
}

__device__ __forceinline__ void cpa16(uint32_t dst, const void* src) {
    asm volatile("cp.async.cg.shared.global [%0], [%1], 16;" :: "r"(dst), "l"(src));
}
__device__ __forceinline__ void cp_commit() {
    asm volatile("cp.async.commit_group;");
}
template <int N_>
__device__ __forceinline__ void cp_wait() {
    asm volatile("cp.async.wait_group %0;" :: "n"(N_));
}

template <int MODE>
__global__ void __launch_bounds__(128, 2) bgemm_k(
    const uint32_t* __restrict__ A, const uint2* __restrict__ B,
    const float* __restrict__ bias, uint32_t* __restrict__ Cw,
    float* __restrict__ Cf, float* __restrict__ out, int M, int N, int K)
{
    extern __shared__ uint32_t sm2[];   // 3 stages x (A[128][36] + Bpair)

    int tid   = threadIdx.x;
    int lane  = tid & 31;
    int warp  = tid >> 5;        // 0..3
    int warpM = warp >> 1;       // 0..1 (64 m-rows)
    int warpN = warp & 1;        // 0..1 (64 n-cols)
    int row0  = blockIdx.y << 7;
    int col0  = blockIdx.x << 7;

    uint32_t sm_base = (uint32_t)__cvta_generic_to_shared(sm2);
    int Kw = K >> 1;

    // A loader: 1024 16B chunks (128 rows x 8); 128 threads -> 8 chunks each.
    int ar = tid >> 3, aw = (tid & 7) << 2;       // row 0..15, wordcol 0..28
    const uint32_t* Ag = A + (size_t)(row0 + ar) * Kw + aw;
    uint32_t a_d = sm_base + (uint32_t)(ar * AS_STRIDE + aw) * 4u;
    // B loader: 4 j-blocks x 4096B; thread covers 16B chunks tid and tid+128.
    uint32_t b_d = sm_base + AS_ELEMS * 4u + (uint32_t)tid * 16u;

    int niter = K >> 6;

    // prologue: prefetch iters 0,1 into stages 0,1
#pragma unroll
    for (int p = 0; p < 2; p++) {
        if (p < niter) {
            uint32_t so = (uint32_t)(p * STAGE_ELEMS) * 4u;
            int k0w = p << 5;
#pragma unroll
            for (int s = 0; s < 8; s++)
                cpa16(a_d + so + (uint32_t)(s * 16 * AS_STRIDE) * 4u,
                      Ag + (size_t)(s * 16) * Kw + k0w);
#pragma unroll
            for (int jj = 0; jj < 4; jj++) {
                size_t jglob = (size_t)(p * 4 + jj);
                const char* src = (const char*)(B + (jglob * N + col0) * 4) + tid * 16;
                cpa16(b_d + so + (uint32_t)jj * 4096u, src);
                cpa16(b_d + so + (uint32_t)jj * 4096u + 2048u, src + 2048);
            }
            cp_commit();
        }
    }

    float acc[4][8][4];
#pragma unroll
    for (int mt = 0; mt < 4; mt++)
#pragma unroll
        for (int nt = 0; nt < 8; nt++)
#pragma unroll
            for (int e = 0; e < 4; e++) acc[mt][nt][e] = 0.f;

    int r = lane >> 2;
    int c = lane & 3;
    int l8 = lane & 7;

    uint32_t a_frag0 = sm_base +
        (uint32_t)((warpM * 64 + l8 + (lane & 8)) * AS_STRIDE + ((lane & 16) >> 2)) * 4u;
    // B lane base within a j-block: ((warpN*64 + r)*4 + c) uint2
    uint32_t b_lane = (uint32_t)(((warpN * 64 + r) * 4 + c) * 8);

    int stage = 0;
    for (int it = 0; it < niter; it++) {
        if (it + 1 < niter) cp_wait<1>();
        else                cp_wait<0>();
        __syncthreads();

        if (it + 2 < niter) {
            int ns = stage + 2; if (ns >= 3) ns -= 3;
            uint32_t so = (uint32_t)(ns * STAGE_ELEMS) * 4u;
            int k0w = (it + 2) << 5;
#pragma unroll
            for (int s = 0; s < 8; s++)
                cpa16(a_d + so + (uint32_t)(s * 16 * AS_STRIDE) * 4u,
                      Ag + (size_t)(s * 16) * Kw + k0w);
#pragma unroll
            for (int jj = 0; jj < 4; jj++) {
                size_t jglob = (size_t)((it + 2) * 4 + jj);
                const char* src = (const char*)(B + (jglob * N + col0) * 4) + tid * 16;
                cpa16(b_d + so + (uint32_t)jj * 4096u, src);
                cpa16(b_d + so + (uint32_t)jj * 4096u + 2048u, src + 2048);
            }
            cp_commit();
        }

        uint32_t abase = a_frag0 + (uint32_t)(stage * STAGE_ELEMS) * 4u;
        uint32_t bbase = sm_base + (uint32_t)(stage * STAGE_ELEMS + AS_ELEMS) * 4u + b_lane;

        // B register double buffer: preload jj=0 (8 n-tiles)
        uint32_t bf[2][8][2];
#pragma unroll
        for (int nt = 0; nt < 8; nt++)
            lds64(bf[0][nt][0], bf[0][nt][1], bbase + (uint32_t)(nt * 256));

#pragma unroll
        for (int jj = 0; jj < 4; jj++) {
            int cur = jj & 1;
            uint32_t af[4][4];
#pragma unroll
            for (int mt = 0; mt < 4; mt++)
                ldsm4(af[mt][0], af[mt][1], af[mt][2], af[mt][3],
                      abase + (uint32_t)(mt * 16 * AS_STRIDE + (jj << 3)) * 4u);
            if (jj < 3) {
                int nxt = cur ^ 1;
#pragma unroll
                for (int nt = 0; nt < 8; nt++)
                    lds64(bf[nxt][nt][0], bf[nxt][nt][1],
                          bbase + (uint32_t)((jj + 1) * 4096) + (uint32_t)(nt * 256));
            }
#pragma unroll
            for (int mt = 0; mt < 4; mt++)
#pragma unroll
                for (int nt = 0; nt < 8; nt++)
                    mma_bf16_a(acc[mt][nt], af[mt][0], af[mt][1], af[mt][2],
                               af[mt][3], bf[cur][nt][0], bf[cur][nt][1]);
        }

        stage = (stage == 2) ? 0 : stage + 1;
    }

    // ---- epilogue ----
    int c2 = c << 1;
    int Nw = N >> 1;
#pragma unroll
    for (int nt = 0; nt < 8; nt++) {
        int gcol = col0 + warpN * 64 + nt * 8 + c2;
        float b0 = bias[gcol], b1 = bias[gcol + 1];
#pragma unroll
        for (int mt = 0; mt < 4; mt++) {
            int grow = row0 + warpM * 64 + mt * 16 + r;
#pragma unroll
            for (int half = 0; half < 2; half++) {
                int rr = grow + half * 8;
                float v0 = acc[mt][nt][half * 2 + 0] + b0;
                float v1 = acc[mt][nt][half * 2 + 1] + b1;
                if (MODE == 0) {
                    Cw[(size_t)rr * Nw + (gcol >> 1)] = packbf(v0, v1);
                } else if (MODE == 2) {
                    Cw[(size_t)rr * Nw + (gcol >> 1)] =
                        packbf(gelu_exact(v0), gelu_exact(v1));
                } else if (MODE == 1) {
                    float2 cur = *(float2*)&Cf[(size_t)rr * N + gcol];
                    cur.x += v0; cur.y += v1;
                    *(float2*)&Cf[(size_t)rr * N + gcol] = cur;
                } else { // MODE 3
                    float2 res = *(float2*)&Cf[(size_t)rr * N + gcol];
                    int b  = rr >> 14;
                    int n  = (rr >> 6) & 255;
                    int l  = rr & 63;
                    int hh = ((n >> 4) << 3) | (l >> 3);
                    int ww = ((n & 15) << 3) | (l & 7);
                    size_t sbase = ((size_t)(b * 512) << 14) + (size_t)(hh << 7) + ww;
                    out[sbase + ((size_t)gcol << 14)]       = v0 + res.x;
                    out[sbase + ((size_t)(gcol + 1) << 14)] = v1 + res.y;
                }
            }
        }
    }
}

// ---------------------------------------------------------------------------
// Launch sequence
// ---------------------------------------------------------------------------
extern "C" void kernel_launch(void* const* d_in, const int* in_sizes, int n_in,
                              void* d_out, int out_size)
{
    const float* x     = (const float*)d_in[0];
    const float* g1    = (const float*)d_in[1];
    const float* be1   = (const float*)d_in[2];
    const float* g2    = (const float*)d_in[3];
    const float* be2   = (const float*)d_in[4];
    const float* w_qkv = (const float*)d_in[5];
    const float* b_qkv = (const float*)d_in[6];
    const float* w_out = (const float*)d_in[7];
    const float* b_out = (const float*)d_in[8];
    const float* w1    = (const float*)d_in[9];
    const float* b1m   = (const float*)d_in[10];
    const float* w2    = (const float*)d_in[11];
    const float* b2m   = (const float*)d_in[12];
    float* out = (float*)d_out;

    float *t;
    uint32_t *xn, *qkv, *o, *hbuf;
    uint2 *wr;
    cudaGetSymbolAddress((void**)&t,    g_t);
    cudaGetSymbolAddress((void**)&xn,   g_xn);
    cudaGetSymbolAddress((void**)&qkv,  g_qkv);
    cudaGetSymbolAddress((void**)&o,    g_o);
    cudaGetSymbolAddress((void**)&hbuf, g_h);
    cudaGetSymbolAddress((void**)&wr,   g_w);

    cudaFuncSetAttribute(bgemm_k<0>, cudaFuncAttributeMaxDynamicSharedMemorySize, BG_SMEM);
    cudaFuncSetAttribute(bgemm_k<1>, cudaFuncAttributeMaxDynamicSharedMemorySize, BG_SMEM);
    cudaFuncSetAttribute(bgemm_k<2>, cudaFuncAttributeMaxDynamicSharedMemorySize, BG_SMEM);
    cudaFuncSetAttribute(bgemm_k<3>, cudaFuncAttributeMaxDynamicSharedMemorySize, BG_SMEM);

    // 0. pack weights to paired-word bf16 layout
    wpack_k<<<WTOT2 / 256, 256>>>(w_qkv, w_out, w1, w2, wr);
    // 1. window partition + LN1
    ln1_part_k<<<TOKS / 8, 256>>>(x, g1, be1, t, xn);
    // 2. qkv = xn @ w_qkv + b_qkv  (bf16 out)
    bgemm_k<0><<<dim3(12, 1024), 128, BG_SMEM>>>(xn, wr + WQKV2_OFF, b_qkv, qkv, nullptr, nullptr, TOKS, 1536, 512);
    // 3. windowed attention (tensor cores)
    attn_k<<<(TOKS / 64) * 8, 128>>>(qkv, o);
    // 4. t += o @ w_out + b_out  (fp32 residual)
    bgemm_k<1><<<dim3(4, 1024), 128, BG_SMEM>>>(o, wr + WOUT2_OFF, b_out, nullptr, t, nullptr, TOKS, 512, 512);
    // 5. LN2 (bf16 out)
    ln2_k<<<TOKS, 128>>>(t, g2, be2, xn);
    // 6. h = gelu(xn @ w1 + b1)  (bf16 out)
    bgemm_k<2><<<dim3(16, 1024), 128, BG_SMEM>>>(xn, wr + W1_2_OFF, b1m, hbuf, nullptr, nullptr, TOKS, 2048, 512);
    // 7. out[x-layout] = t + h @ w2 + b2  (fused un-partition)
    bgemm_k<3><<<dim3(4, 1024), 128, BG_SMEM>>>(hbuf, wr + W2_2_OFF, b2m, nullptr, t, out, TOKS, 512, 2048);
}

// round 15
// speedup vs baseline: 1.0457x; 1.0457x over previous
#include <cuda_runtime.h>
#include <math.h>
#include <stdint.h>

// ---------------------------------------------------------------------------
// B=8, C=512, H=W=128, WS=8, NH=8, hd=64, L=64, N=256 windows/batch
// TOKS = 8*256*64 = 131072
// ---------------------------------------------------------------------------
#define TOKS 131072

__device__ float    g_t  [(size_t)TOKS * 512];   // residual (fp32)
__device__ uint32_t g_xn [(size_t)TOKS * 256];   // LN out (bf16x2)
__device__ uint32_t g_qkv[(size_t)TOKS * 768];   // qkv (bf16x2)
__device__ uint32_t g_o  [(size_t)TOKS * 256];   // attn out (bf16x2)
__device__ uint32_t g_h  [(size_t)TOKS * 1024];  // mlp hidden (bf16x2)

// weights packed as PAIRED k-words (uint2):
//   Bp[j][n][c] = ( word(8j+c, n), word(8j+c+4, n) )
#define WQKV2_OFF 0
#define WOUT2_OFF 196608
#define W1_2_OFF  262144
#define W2_2_OFF  524288
#define WTOT2     786432
__device__ uint2 g_w[WTOT2];

__device__ __forceinline__ uint32_t packbf(float lo, float hi) {
    uint32_t u;
    asm("cvt.rn.bf16x2.f32 %0, %1, %2;" : "=r"(u) : "f"(hi), "f"(lo));
    return u;
}

// ---------------------------------------------------------------------------
// Weight pack: fp32 [K][N] -> paired-word uint2 layout
// ---------------------------------------------------------------------------
__global__ void __launch_bounds__(256) wpack_k(
    const float* __restrict__ wqkv, const float* __restrict__ wout,
    const float* __restrict__ w1, const float* __restrict__ w2,
    uint2* __restrict__ dst)
{
    int idx = blockIdx.x * 256 + threadIdx.x;
    const float* src;
    int N, u;
    if (idx < WOUT2_OFF)      { src = wqkv; N = 1536; u = idx; }
    else if (idx < W1_2_OFF)  { src = wout; N = 512;  u = idx - WOUT2_OFF; }
    else if (idx < W2_2_OFF)  { src = w1;   N = 2048; u = idx - W1_2_OFF; }
    else                      { src = w2;   N = 512;  u = idx - W2_2_OFF; }
    int c  = u & 3;
    int nc = u >> 2;
    int n  = nc % N;
    int j  = nc / N;
    int kp0 = 8 * j + c;
    int kp1 = kp0 + 4;
    uint2 out;
    out.x = packbf(src[(2 * kp0) * N + n], src[(2 * kp0 + 1) * N + n]);
    out.y = packbf(src[(2 * kp1) * N + n], src[(2 * kp1 + 1) * N + n]);
    dst[idx] = out;
}

// ---------------------------------------------------------------------------
// Window partition + LayerNorm1, coalesced (one CTA per 8-token window row).
// ---------------------------------------------------------------------------
__global__ void __launch_bounds__(256) ln1_part_k(
    const float* __restrict__ x, const float* __restrict__ gamma,
    const float* __restrict__ beta, float* __restrict__ t, uint32_t* __restrict__ xn)
{
    int tid  = threadIdx.x;
    int tok0 = blockIdx.x << 3;
    int b  = tok0 >> 14;
    int n  = (tok0 >> 6) & 255;
    int l0 = tok0 & 63;
    int h  = ((n >> 4) << 3) | (l0 >> 3);
    int w0 = (n & 15) << 3;
    int c0 = tid << 1;

    size_t base0 = ((size_t)(b * 512 + c0)) * 16384 + (size_t)(h << 7) + w0;

    float va[8], vb[8];
    {
        float4 p0 = *(const float4*)(x + base0);
        float4 p1 = *(const float4*)(x + base0 + 4);
        float4 p2 = *(const float4*)(x + base0 + 16384);
        float4 p3 = *(const float4*)(x + base0 + 16388);
        va[0]=p0.x; va[1]=p0.y; va[2]=p0.z; va[3]=p0.w;
        va[4]=p1.x; va[5]=p1.y; va[6]=p1.z; va[7]=p1.w;
        vb[0]=p2.x; vb[1]=p2.y; vb[2]=p2.z; vb[3]=p2.w;
        vb[4]=p3.x; vb[5]=p3.y; vb[6]=p3.z; vb[7]=p3.w;
    }

    float s[8], s2[8];
#pragma unroll
    for (int ww = 0; ww < 8; ww++) {
        s[ww]  = va[ww] + vb[ww];
        s2[ww] = va[ww] * va[ww] + vb[ww] * vb[ww];
    }
#pragma unroll
    for (int off = 16; off; off >>= 1) {
#pragma unroll
        for (int ww = 0; ww < 8; ww++) {
            s[ww]  += __shfl_xor_sync(0xffffffffu, s[ww],  off);
            s2[ww] += __shfl_xor_sync(0xffffffffu, s2[ww], off);
        }
    }

    __shared__ float red[8][16];
    __shared__ float mr[16];
    int warp = tid >> 5, lane = tid & 31;
    if (lane == 0) {
#pragma unroll
        for (int ww = 0; ww < 8; ww++) {
            red[warp][ww]     = s[ww];
            red[warp][8 + ww] = s2[ww];
        }
    }
    __syncthreads();
    if (tid < 8) {
        float ts = 0.f, ts2 = 0.f;
#pragma unroll
        for (int wp = 0; wp < 8; wp++) {
            ts  += red[wp][tid];
            ts2 += red[wp][8 + tid];
        }
        float mu  = ts * (1.f / 512.f);
        float var = ts2 * (1.f / 512.f) - mu * mu;
        mr[tid]     = mu;
        mr[8 + tid] = rsqrtf(var + 1e-5f);
    }
    __syncthreads();

    float ga = gamma[c0], gb = gamma[c0 + 1];
    float ba = beta[c0],  bb = beta[c0 + 1];
#pragma unroll
    for (int ww = 0; ww < 8; ww++) {
        int tok = tok0 + ww;
        float mu = mr[ww], rs = mr[8 + ww];
        float n0 = (va[ww] - mu) * rs * ga + ba;
        float n1 = (vb[ww] - mu) * rs * gb + bb;
        *(float2*)&t[(size_t)tok * 512 + c0] = make_float2(va[ww], vb[ww]);
        xn[(size_t)tok * 256 + tid] = packbf(n0, n1);
    }
}

// ---------------------------------------------------------------------------
// LayerNorm2: fp32 src (t) -> bf16 xn
// ---------------------------------------------------------------------------
__global__ void __launch_bounds__(128) ln2_k(
    const float* __restrict__ src, const float* __restrict__ gamma,
    const float* __restrict__ beta, uint32_t* __restrict__ xn)
{
    int tok = blockIdx.x;
    int tid = threadIdx.x;
    int c0 = tid << 2;
    float4 v4 = *(const float4*)&src[(size_t)tok * 512 + c0];
    float v[4] = {v4.x, v4.y, v4.z, v4.w};
    float s = v[0] + v[1] + v[2] + v[3];
    float s2 = v[0]*v[0] + v[1]*v[1] + v[2]*v[2] + v[3]*v[3];
#pragma unroll
    for (int off = 16; off; off >>= 1) {
        s  += __shfl_xor_sync(0xffffffffu, s,  off);
        s2 += __shfl_xor_sync(0xffffffffu, s2, off);
    }
    __shared__ float sh[8];
    int wid = tid >> 5, lane = tid & 31;
    if (lane == 0) { sh[wid] = s; sh[4 + wid] = s2; }
    __syncthreads();
    s  = sh[0] + sh[1] + sh[2] + sh[3];
    s2 = sh[4] + sh[5] + sh[6] + sh[7];
    float mu  = s  * (1.f / 512.f);
    float var = s2 * (1.f / 512.f) - mu * mu;
    float rs  = rsqrtf(var + 1e-5f);

    float nv[4];
#pragma unroll
    for (int k = 0; k < 4; k++)
        nv[k] = (v[k] - mu) * rs * gamma[c0 + k] + beta[c0 + k];
    uint2 pw = make_uint2(packbf(nv[0], nv[1]), packbf(nv[2], nv[3]));
    *(uint2*)&xn[(size_t)tok * 256 + (tid << 1)] = pw;
}

// ---------------------------------------------------------------------------
// ldmatrix / mma helpers
// ---------------------------------------------------------------------------
__device__ __forceinline__ void ldsm4(uint32_t& r0, uint32_t& r1, uint32_t& r2,
                                      uint32_t& r3, uint32_t addr) {
    asm volatile("ldmatrix.sync.aligned.m8n8.x4.shared.b16 {%0,%1,%2,%3}, [%4];"
                 : "=r"(r0), "=r"(r1), "=r"(r2), "=r"(r3) : "r"(addr));
}
__device__ __forceinline__ void ldsm2(uint32_t& r0, uint32_t& r1, uint32_t addr) {
    asm volatile("ldmatrix.sync.aligned.m8n8.x2.shared.b16 {%0,%1}, [%2];"
                 : "=r"(r0), "=r"(r1) : "r"(addr));
}
__device__ __forceinline__ void ldsm2t(uint32_t& r0, uint32_t& r1, uint32_t addr) {
    asm volatile("ldmatrix.sync.aligned.m8n8.x2.trans.shared.b16 {%0,%1}, [%2];"
                 : "=r"(r0), "=r"(r1) : "r"(addr));
}
__device__ __forceinline__ void lds64(uint32_t& r0, uint32_t& r1, uint32_t addr) {
    asm volatile("ld.shared.v2.u32 {%0,%1}, [%2];"
                 : "=r"(r0), "=r"(r1) : "r"(addr));
}
__device__ __forceinline__ void mma_bf16_a(float* d, uint32_t a0, uint32_t a1,
                                           uint32_t a2, uint32_t a3,
                                           uint32_t b0, uint32_t b1) {
    asm volatile(
        "mma.sync.aligned.m16n8k16.row.col.f32.bf16.bf16.f32 "
        "{%0,%1,%2,%3}, {%4,%5,%6,%7}, {%8,%9}, {%0,%1,%2,%3};"
        : "+f"(d[0]), "+f"(d[1]), "+f"(d[2]), "+f"(d[3])
        : "r"(a0), "r"(a1), "r"(a2), "r"(a3), "r"(b0), "r"(b1));
}

// ---------------------------------------------------------------------------
// Tensor-core attention (unchanged, 132us)
// ---------------------------------------------------------------------------
#define ATS 36

__global__ void __launch_bounds__(128) attn_k(
    const uint32_t* __restrict__ qkv, uint32_t* __restrict__ o)
{
    __shared__ uint32_t sm[3 * 64 * ATS];
    uint32_t* qs = sm;
    uint32_t* ks = sm + 64 * ATS;
    uint32_t* vs = sm + 2 * 64 * ATS;

    int tid  = threadIdx.x;
    int lane = tid & 31;
    int warp = tid >> 5;
    int win  = blockIdx.x >> 3;
    int head = blockIdx.x & 7;

    {
        int row = tid >> 1, half = tid & 1;
        size_t gbase = (size_t)(win * 64 + row) * 768 + head * 32 + half * 16;
        int sbase = row * ATS + half * 16;
#pragma unroll
        for (int sec = 0; sec < 3; sec++) {
            const uint4* src = (const uint4*)(qkv + gbase + sec * 256);
            uint4* dst = (uint4*)(sm + sec * 64 * ATS + sbase);
            dst[0] = src[0]; dst[1] = src[1]; dst[2] = src[2]; dst[3] = src[3];
        }
    }
    __syncthreads();

    uint32_t qs_u = (uint32_t)__cvta_generic_to_shared(qs);
    uint32_t ks_u = (uint32_t)__cvta_generic_to_shared(ks);
    uint32_t vs_u = (uint32_t)__cvta_generic_to_shared(vs);

    int r0  = warp << 4;
    int l8  = lane & 7;
    int l16 = lane & 15;

    uint32_t qaddr = qs_u + (uint32_t)((r0 + l8 + (lane & 8)) * ATS + ((lane & 16) >> 2)) * 4u;
    uint32_t kaddr = ks_u + (uint32_t)((l16 & 7) * ATS + ((l16 & 8) >> 1)) * 4u;
    uint32_t vaddr = vs_u + (uint32_t)(((l16 & 7) + (l16 & 8)) * ATS) * 4u;

    float sacc[8][4];
#pragma unroll
    for (int nt = 0; nt < 8; nt++)
#pragma unroll
        for (int e = 0; e < 4; e++) sacc[nt][e] = 0.f;

#pragma unroll
    for (int kt = 0; kt < 4; kt++) {
        uint32_t a0, a1, a2, a3;
        ldsm4(a0, a1, a2, a3, qaddr + (uint32_t)(kt * 8) * 4u);
#pragma unroll
        for (int nt = 0; nt < 8; nt++) {
            uint32_t b0, b1;
            ldsm2(b0, b1, kaddr + (uint32_t)(nt * 8 * ATS + kt * 8) * 4u);
            mma_bf16_a(sacc[nt], a0, a1, a2, a3, b0, b1);
        }
    }

    const float scl = 1.f / 4096.f;
#pragma unroll
    for (int nt = 0; nt < 8; nt++)
#pragma unroll
        for (int e = 0; e < 4; e++) sacc[nt][e] *= scl;

    float m0 = -1e30f, m1 = -1e30f;
#pragma unroll
    for (int nt = 0; nt < 8; nt++) {
        m0 = fmaxf(m0, fmaxf(sacc[nt][0], sacc[nt][1]));
        m1 = fmaxf(m1, fmaxf(sacc[nt][2], sacc[nt][3]));
    }
    m0 = fmaxf(m0, __shfl_xor_sync(0xffffffffu, m0, 1));
    m0 = fmaxf(m0, __shfl_xor_sync(0xffffffffu, m0, 2));
    m1 = fmaxf(m1, __shfl_xor_sync(0xffffffffu, m1, 1));
    m1 = fmaxf(m1, __shfl_xor_sync(0xffffffffu, m1, 2));

    float sum0 = 0.f, sum1 = 0.f;
#pragma unroll
    for (int nt = 0; nt < 8; nt++) {
        sacc[nt][0] = __expf(sacc[nt][0] - m0); sum0 += sacc[nt][0];
        sacc[nt][1] = __expf(sacc[nt][1] - m0); sum0 += sacc[nt][1];
        sacc[nt][2] = __expf(sacc[nt][2] - m1); sum1 += sacc[nt][2];
        sacc[nt][3] = __expf(sacc[nt][3] - m1); sum1 += sacc[nt][3];
    }
    sum0 += __shfl_xor_sync(0xffffffffu, sum0, 1);
    sum0 += __shfl_xor_sync(0xffffffffu, sum0, 2);
    sum1 += __shfl_xor_sync(0xffffffffu, sum1, 1);
    sum1 += __shfl_xor_sync(0xffffffffu, sum1, 2);
    float inv0 = 1.f / sum0, inv1 = 1.f / sum1;

    uint32_t pw[4][4];
#pragma unroll
    for (int kt = 0; kt < 4; kt++) {
        pw[kt][0] = packbf(sacc[2*kt    ][0] * inv0, sacc[2*kt    ][1] * inv0);
        pw[kt][1] = packbf(sacc[2*kt    ][2] * inv1, sacc[2*kt    ][3] * inv1);
        pw[kt][2] = packbf(sacc[2*kt + 1][0] * inv0, sacc[2*kt + 1][1] * inv0);
        pw[kt][3] = packbf(sacc[2*kt + 1][2] * inv1, sacc[2*kt + 1][3] * inv1);
    }

    float oacc[8][4];
#pragma unroll
    for (int nt = 0; nt < 8; nt++)
#pragma unroll
        for (int e = 0; e < 4; e++) oacc[nt][e] = 0.f;

#pragma unroll
    for (int kt = 0; kt < 4; kt++) {
#pragma unroll
        for (int nt = 0; nt < 8; nt++) {
            uint32_t b0, b1;
            ldsm2t(b0, b1, vaddr + (uint32_t)(kt * 16 * ATS + nt * 4) * 4u);
            mma_bf16_a(oacc[nt], pw[kt][0], pw[kt][1], pw[kt][2], pw[kt][3], b0, b1);
        }
    }

    int r  = lane >> 2;
    int cq = lane & 3;
    uint32_t* ob = o + (size_t)(win * 64 + r0 + r) * 256 + head * 32 + cq;
#pragma unroll
    for (int nt = 0; nt < 8; nt++) {
        ob[nt * 4]            = packbf(oacc[nt][0], oacc[nt][1]);
        ob[8 * 256 + nt * 4]  = packbf(oacc[nt][2], oacc[nt][3]);
    }
}

// ---------------------------------------------------------------------------
// BF16 tensor-core GEMM (R13 mainloop): BK=64, 3-stage cp.async, ldsm4 A,
// paired LDS.64 B with register double buffering. 256 thr, 8 warps (2Mx4N).
// MODE 0/2 epilogue now smem-staged for fully coalesced 256B stores.
//   MODE 0: Cw = bf16(A@B + bias)
//   MODE 1: Cf += A@B + bias
//   MODE 2: Cw = bf16(gelu(A@B + bias))
//   MODE 3: out[x-layout] = Cf + A@B + bias
// ---------------------------------------------------------------------------
#define AS_STRIDE 36
#define AS_ELEMS (128 * AS_STRIDE)          // 4608 words
#define BS_ELEMS 4096                       // words (2048 uint2)
#define STAGE_ELEMS (AS_ELEMS + BS_ELEMS)   // 8704 words
#define BG_SMEM (3 * STAGE_ELEMS * 4)       // 104448 B
#define OST 68                              // output stage row stride (words)

__device__ __forceinline__ float gelu_exact(float v) {
    return 0.5f * v * (1.0f + erff(v * 0.70710678118654752440f));
}

__device__ __forceinline__ void cpa16(uint32_t dst, const void* src) {
    asm volatile("cp.async.cg.shared.global [%0], [%1], 16;" :: "r"(dst), "l"(src));
}
__device__ __forceinline__ void cp_commit() {
    asm volatile("cp.async.commit_group;");
}
template <int N_>
__device__ __forceinline__ void cp_wait() {
    asm volatile("cp.async.wait_group %0;" :: "n"(N_));
}

template <int MODE>
__global__ void __launch_bounds__(256, 2) bgemm_k(
    const uint32_t* __restrict__ A, const uint2* __restrict__ B,
    const float* __restrict__ bias, uint32_t* __restrict__ Cw,
    float* __restrict__ Cf, float* __restrict__ out, int M, int N, int K)
{
    extern __shared__ uint32_t sm2[];   // 3 stages x (A[128][36] + Bpair)

    int tid   = threadIdx.x;
    int lane  = tid & 31;
    int warp  = tid >> 5;
    int warpM = warp >> 2;
    int warpN = warp & 3;
    int row0  = blockIdx.y << 7;
    int col0  = blockIdx.x << 7;

    uint32_t sm_base = (uint32_t)__cvta_generic_to_shared(sm2);
    int Kw = K >> 1;

    int ar = tid >> 3, aw = (tid & 7) << 2;
    const uint32_t* Ag = A + (size_t)(row0 + ar) * Kw + aw;
    uint32_t a_d = sm_base + (uint32_t)(ar * AS_STRIDE + aw) * 4u;
    uint32_t b_d = sm_base + AS_ELEMS * 4u + (uint32_t)tid * 16u;

    int niter = K >> 6;

    // prologue: prefetch iters 0,1 into stages 0,1
#pragma unroll
    for (int p = 0; p < 2; p++) {
        if (p < niter) {
            uint32_t so = (uint32_t)(p * STAGE_ELEMS) * 4u;
            int k0w = p << 5;
#pragma unroll
            for (int s = 0; s < 4; s++)
                cpa16(a_d + so + (uint32_t)(s * 32 * AS_STRIDE) * 4u,
                      Ag + (size_t)(s * 32) * Kw + k0w);
#pragma unroll
            for (int jj = 0; jj < 4; jj++) {
                size_t jglob = (size_t)(p * 4 + jj);
                const char* src = (const char*)(B + (jglob * N + col0) * 4) + tid * 16;
                cpa16(b_d + so + (uint32_t)jj * 4096u, src);
            }
            cp_commit();
        }
    }

    float acc[4][4][4];
#pragma unroll
    for (int mt = 0; mt < 4; mt++)
#pragma unroll
        for (int nt = 0; nt < 4; nt++)
#pragma unroll
            for (int e = 0; e < 4; e++) acc[mt][nt][e] = 0.f;

    int r = lane >> 2;
    int c = lane & 3;
    int l8 = lane & 7;

    uint32_t a_frag0 = sm_base +
        (uint32_t)((warpM * 64 + l8 + (lane & 8)) * AS_STRIDE + ((lane & 16) >> 2)) * 4u;
    uint32_t b_lane = (uint32_t)(((warpN * 32 + r) * 4 + c) * 8);

    int stage = 0;
    for (int it = 0; it < niter; it++) {
        if (it + 1 < niter) cp_wait<1>();
        else                cp_wait<0>();
        __syncthreads();

        if (it + 2 < niter) {
            int ns = stage + 2; if (ns >= 3) ns -= 3;
            uint32_t so = (uint32_t)(ns * STAGE_ELEMS) * 4u;
            int k0w = (it + 2) << 5;
#pragma unroll
            for (int s = 0; s < 4; s++)
                cpa16(a_d + so + (uint32_t)(s * 32 * AS_STRIDE) * 4u,
                      Ag + (size_t)(s * 32) * Kw + k0w);
#pragma unroll
            for (int jj = 0; jj < 4; jj++) {
                size_t jglob = (size_t)((it + 2) * 4 + jj);
                const char* src = (const char*)(B + (jglob * N + col0) * 4) + tid * 16;
                cpa16(b_d + so + (uint32_t)jj * 4096u, src);
            }
            cp_commit();
        }

        uint32_t abase = a_frag0 + (uint32_t)(stage * STAGE_ELEMS) * 4u;
        uint32_t bbase = sm_base + (uint32_t)(stage * STAGE_ELEMS + AS_ELEMS) * 4u + b_lane;

        uint32_t bf[2][4][2];
#pragma unroll
        for (int nt = 0; nt < 4; nt++)
            lds64(bf[0][nt][0], bf[0][nt][1], bbase + (uint32_t)(nt * 256));

#pragma unroll
        for (int jj = 0; jj < 4; jj++) {
            int cur = jj & 1;
            uint32_t af[4][4];
#pragma unroll
            for (int mt = 0; mt < 4; mt++)
                ldsm4(af[mt][0], af[mt][1], af[mt][2], af[mt][3],
                      abase + (uint32_t)(mt * 16 * AS_STRIDE + (jj << 3)) * 4u);
            if (jj < 3) {
                int nxt = cur ^ 1;
#pragma unroll
                for (int nt = 0; nt < 4; nt++)
                    lds64(bf[nxt][nt][0], bf[nxt][nt][1],
                          bbase + (uint32_t)((jj + 1) * 4096) + (uint32_t)(nt * 256));
            }
#pragma unroll
            for (int mt = 0; mt < 4; mt++)
#pragma unroll
                for (int nt = 0; nt < 4; nt++)
                    mma_bf16_a(acc[mt][nt], af[mt][0], af[mt][1], af[mt][2],
                               af[mt][3], bf[cur][nt][0], bf[cur][nt][1]);
        }

        stage = (stage == 2) ? 0 : stage + 1;
    }

    // ---- epilogue ----
    int c2 = c << 1;
    int Nw = N >> 1;

    if (MODE == 0 || MODE == 2) {
        // stage packed bf16 words to smem, then fully-coalesced uint2 stores
        __syncthreads();   // mainloop smem reads complete before overwrite
        uint32_t* stg = sm2;   // 128 rows x OST words
#pragma unroll
        for (int nt = 0; nt < 4; nt++) {
            int gcol = col0 + warpN * 32 + nt * 8 + c2;
            float b0 = bias[gcol], b1 = bias[gcol + 1];
            int wcol = warpN * 16 + nt * 4 + c;
#pragma unroll
            for (int mt = 0; mt < 4; mt++) {
                int rloc = warpM * 64 + mt * 16 + r;
#pragma unroll
                for (int half = 0; half < 2; half++) {
                    float v0 = acc[mt][nt][half * 2 + 0] + b0;
                    float v1 = acc[mt][nt][half * 2 + 1] + b1;
                    if (MODE == 2) { v0 = gelu_exact(v0); v1 = gelu_exact(v1); }
                    stg[(rloc + half * 8) * OST + wcol] = packbf(v0, v1);
                }
            }
        }
        __syncthreads();
        int colw0 = col0 >> 1;
#pragma unroll
        for (int s = 0; s < 16; s++) {
            int idx  = s * 256 + tid;
            int rowl = idx >> 5;        // 0..127
            int cw   = idx & 31;        // uint2 index 0..31
            uint2 v = *(uint2*)&stg[rowl * OST + cw * 2];
            *(uint2*)&Cw[(size_t)(row0 + rowl) * Nw + colw0 + cw * 2] = v;
        }
    } else {
#pragma unroll
        for (int nt = 0; nt < 4; nt++) {
            int gcol = col0 + warpN * 32 + nt * 8 + c2;
            float b0 = bias[gcol], b1 = bias[gcol + 1];
#pragma unroll
            for (int mt = 0; mt < 4; mt++) {
                int grow = row0 + warpM * 64 + mt * 16 + r;
#pragma unroll
                for (int half = 0; half < 2; half++) {
                    int rr = grow + half * 8;
                    float v0 = acc[mt][nt][half * 2 + 0] + b0;
                    float v1 = acc[mt][nt][half * 2 + 1] + b1;
                    if (MODE == 1) {
                        float2 cur = *(float2*)&Cf[(size_t)rr * N + gcol];
                        cur.x += v0; cur.y += v1;
                        *(float2*)&Cf[(size_t)rr * N + gcol] = cur;
                    } else { // MODE 3
                        float2 res = *(float2*)&Cf[(size_t)rr * N + gcol];
                        int b  = rr >> 14;
                        int n  = (rr >> 6) & 255;
                        int l  = rr & 63;
                        int hh = ((n >> 4) << 3) | (l >> 3);
                        int ww = ((n & 15) << 3) | (l & 7);
                        size_t sbase = ((size_t)(b * 512) << 14) + (size_t)(hh << 7) + ww;
                        out[sbase + ((size_t)gcol << 14)]       = v0 + res.x;
                        out[sbase + ((size_t)(gcol + 1) << 14)] = v1 + res.y;
                    }
                }
            }
        }
    }
}

// ---------------------------------------------------------------------------
// Launch sequence
// ---------------------------------------------------------------------------
extern "C" void kernel_launch(void* const* d_in, const int* in_sizes, int n_in,
                              void* d_out, int out_size)
{
    const float* x     = (const float*)d_in[0];
    const float* g1    = (const float*)d_in[1];
    const float* be1   = (const float*)d_in[2];
    const float* g2    = (const float*)d_in[3];
    const float* be2   = (const float*)d_in[4];
    const float* w_qkv = (const float*)d_in[5];
    const float* b_qkv = (const float*)d_in[6];
    const float* w_out = (const float*)d_in[7];
    const float* b_out = (const float*)d_in[8];
    const float* w1    = (const float*)d_in[9];
    const float* b1m   = (const float*)d_in[10];
    const float* w2    = (const float*)d_in[11];
    const float* b2m   = (const float*)d_in[12];
    float* out = (float*)d_out;

    float *t;
    uint32_t *xn, *qkv, *o, *hbuf;
    uint2 *wr;
    cudaGetSymbolAddress((void**)&t,    g_t);
    cudaGetSymbolAddress((void**)&xn,   g_xn);
    cudaGetSymbolAddress((void**)&qkv,  g_qkv);
    cudaGetSymbolAddress((void**)&o,    g_o);
    cudaGetSymbolAddress((void**)&hbuf, g_h);
    cudaGetSymbolAddress((void**)&wr,   g_w);

    cudaFuncSetAttribute(bgemm_k<0>, cudaFuncAttributeMaxDynamicSharedMemorySize, BG_SMEM);
    cudaFuncSetAttribute(bgemm_k<1>, cudaFuncAttributeMaxDynamicSharedMemorySize, BG_SMEM);
    cudaFuncSetAttribute(bgemm_k<2>, cudaFuncAttributeMaxDynamicSharedMemorySize, BG_SMEM);
    cudaFuncSetAttribute(bgemm_k<3>, cudaFuncAttributeMaxDynamicSharedMemorySize, BG_SMEM);

    // 0. pack weights to paired-word bf16 layout
    wpack_k<<<WTOT2 / 256, 256>>>(w_qkv, w_out, w1, w2, wr);
    // 1. window partition + LN1
    ln1_part_k<<<TOKS / 8, 256>>>(x, g1, be1, t, xn);
    // 2. qkv = xn @ w_qkv + b_qkv  (bf16 out, staged stores)
    bgemm_k<0><<<dim3(12, 1024), 256, BG_SMEM>>>(xn, wr + WQKV2_OFF, b_qkv, qkv, nullptr, nullptr, TOKS, 1536, 512);
    // 3. windowed attention (tensor cores)
    attn_k<<<(TOKS / 64) * 8, 128>>>(qkv, o);
    // 4. t += o @ w_out + b_out  (fp32 residual)
    bgemm_k<1><<<dim3(4, 1024), 256, BG_SMEM>>>(o, wr + WOUT2_OFF, b_out, nullptr, t, nullptr, TOKS, 512, 512);
    // 5. LN2 (bf16 out)
    ln2_k<<<TOKS, 128>>>(t, g2, be2, xn);
    // 6. h = gelu(xn @ w1 + b1)  (bf16 out, staged stores)
    bgemm_k<2><<<dim3(16, 1024), 256, BG_SMEM>>>(xn, wr + W1_2_OFF, b1m, hbuf, nullptr, nullptr, TOKS, 2048, 512);
    // 7. out[x-layout] = t + h @ w2 + b2  (fused un-partition)
    bgemm_k<3><<<dim3(4, 1024), 256, BG_SMEM>>>(hbuf, wr + W2_2_OFF, b2m, nullptr, t, out, TOKS, 512, 2048);
}